// round 17
// baseline (speedup 1.0000x reference)
#include <cuda_runtime.h>
#include <math.h>

// Chamfer distance, B=4, N=M=8192, 3D.
// d_out (float32): dist1[B*N] | dist2[B*M] | idx1[B*N] | idx2[B*M]
// R16 instruction economy (2 queries/thread share pipelined LDS) +
// R15 grid shape (2048 blocks -> full occupancy): 8 segments of 128
// candidates, 16 slots x 8 segments = 128 threads, 32 queries/block.
//  - packed f32x2 FMA body (proven: no argmin flips, rel_err 4.5e-8)
//  - software-pipelined group operands (R15-proven)
//  - branchless chunk tracking; winning group recomputed from the SAME smem
//    with the SAME packed helpers (bit-exact index recovery)
//  - exact first-occurrence ties: strict < across groups/chunks, descending
//    in-group scan, lexicographic (d, idx) combine across segments

#define QPB 128            // 16 slots x 8 segments; 2 queries per thread
#define NQ_BLK 32          // queries per block
#define NSLOT 16
#define NSEG 8
#define CH 1024            // candidates staged per chunk
#define SEG 128            // candidates per segment per chunk
#define NGRP (SEG / 8)     // 16 groups per chunk per segment

typedef unsigned long long u64;

__device__ __forceinline__ void unpack2(float& lo, float& hi, u64 v) {
    asm("mov.b64 {%0, %1}, %2;" : "=f"(lo), "=f"(hi) : "l"(v));
}
__device__ __forceinline__ u64 pack2(float lo, float hi) {
    u64 r;
    asm("mov.b64 %0, {%1, %2};" : "=l"(r) : "f"(lo), "f"(hi));
    return r;
}
__device__ __forceinline__ u64 add2(u64 a, u64 b) {
    u64 r;
    asm("add.rn.f32x2 %0, %1, %2;" : "=l"(r) : "l"(a), "l"(b));
    return r;
}
__device__ __forceinline__ u64 mul2(u64 a, u64 b) {
    u64 r;
    asm("mul.rn.f32x2 %0, %1, %2;" : "=l"(r) : "l"(a), "l"(b));
    return r;
}
__device__ __forceinline__ u64 fma2(u64 a, u64 b, u64 c) {
    u64 r;
    asm("fma.rn.f32x2 %0, %1, %2, %3;" : "=l"(r) : "l"(a), "l"(b), "l"(c));
    return r;
}
__device__ __forceinline__ float negf(float x) {
    return __int_as_float(__float_as_int(x) ^ 0x80000000);
}

// Distances for one 8-candidate group from its 6 preloaded 16B vectors.
// IDENTICAL op sequence everywhere -> bit-exact agreement between the hot
// loop and the recovery path.
__device__ __forceinline__ void group_dists_v(
    ulonglong2 X0, ulonglong2 X1, ulonglong2 Y0, ulonglong2 Y1,
    ulonglong2 Z0, ulonglong2 Z1,
    u64 pxx, u64 pyy, u64 pzz,
    float& d0, float& d1, float& d2, float& d3,
    float& d4, float& d5, float& d6, float& d7)
{
    u64 dx0 = add2(pxx, X0.x), dx1 = add2(pxx, X0.y);
    u64 dx2 = add2(pxx, X1.x), dx3 = add2(pxx, X1.y);
    u64 dy0 = add2(pyy, Y0.x), dy1 = add2(pyy, Y0.y);
    u64 dy2 = add2(pyy, Y1.x), dy3 = add2(pyy, Y1.y);
    u64 dz0 = add2(pzz, Z0.x), dz1 = add2(pzz, Z0.y);
    u64 dz2 = add2(pzz, Z1.x), dz3 = add2(pzz, Z1.y);
    u64 d01 = fma2(dx0, dx0, fma2(dy0, dy0, mul2(dz0, dz0)));
    u64 d23 = fma2(dx1, dx1, fma2(dy1, dy1, mul2(dz1, dz1)));
    u64 d45 = fma2(dx2, dx2, fma2(dy2, dy2, mul2(dz2, dz2)));
    u64 d67 = fma2(dx3, dx3, fma2(dy3, dy3, mul2(dz3, dz3)));
    unpack2(d0, d1, d01);
    unpack2(d2, d3, d23);
    unpack2(d4, d5, d45);
    unpack2(d6, d7, d67);
}

// In-group first-occurrence argmin (descending scan on the min's registers).
__device__ __forceinline__ int group_argmin(
    float m, int jb,
    float d0, float d1, float d2, float d3,
    float d4, float d5, float d6, float d7)
{
    int s = jb + 7;
    if (d6 == m) s = jb + 6;
    if (d5 == m) s = jb + 5;
    if (d4 == m) s = jb + 4;
    if (d3 == m) s = jb + 3;
    if (d2 == m) s = jb + 2;
    if (d1 == m) s = jb + 1;
    if (d0 == m) s = jb;
    return s;
}

__global__ __launch_bounds__(QPB) void chamfer_kernel(
    const float* __restrict__ xyz1,
    const float* __restrict__ xyz2,
    float* __restrict__ out,
    int N, int M, int B)
{
    __shared__ __align__(16) float smem_f[3 * CH];   // negated SoA: x | y | z
    __shared__ float rbest[NSEG * NQ_BLK];
    __shared__ int   rbi[NSEG * NQ_BLK];

    float* sx = smem_f;
    float* sy = smem_f + CH;
    float* sz = smem_f + 2 * CH;

    const int dir = blockIdx.z;   // 0: xyz1->xyz2, 1: xyz2->xyz1
    const int b   = blockIdx.y;

    const float* q; const float* c;
    float* outd; float* outi;
    int Nq, Nc;
    if (dir == 0) {
        q = xyz1; c = xyz2; Nq = N; Nc = M;
        outd = out;
        outi = out + (size_t)B * N + (size_t)B * M;
    } else {
        q = xyz2; c = xyz1; Nq = M; Nc = N;
        outd = out + (size_t)B * N;
        outi = out + (size_t)B * N + (size_t)B * M + (size_t)B * N;
    }

    const int tid  = threadIdx.x;
    const int slot = tid & (NSLOT - 1);   // 0..15
    const int seg  = tid >> 4;            // 0..7: candidate segment
    const int qi0  = blockIdx.x * NQ_BLK + slot;   // query A
    const int qi1  = qi0 + NSLOT;                  // query B

    const float* qa  = q + ((size_t)b * Nq + qi0) * 3;
    const float* qbp = q + ((size_t)b * Nq + qi1) * 3;
    const float* cb  = c + (size_t)b * Nc * 3;

    const u64 paxx = pack2(qa[0], qa[0]);
    const u64 payy = pack2(qa[1], qa[1]);
    const u64 pazz = pack2(qa[2], qa[2]);
    const u64 pbxx = pack2(qbp[0], qbp[0]);
    const u64 pbyy = pack2(qbp[1], qbp[1]);
    const u64 pbzz = pack2(qbp[2], qbp[2]);

    // Segment views of the staged chunk (64-bit lanes, LDS.128 pairs).
    const ulonglong2* sxv = (const ulonglong2*)(sx + seg * SEG);
    const ulonglong2* syv = (const ulonglong2*)(sy + seg * SEG);
    const ulonglong2* szv = (const ulonglong2*)(sz + seg * SEG);

    float bestA = INFINITY, bestB = INFINITY;
    int   biA = 0, biB = 0;

    for (int base = 0; base < Nc; base += CH) {
        __syncthreads();   // protect smem from previous chunk's readers
        for (int t = tid; t < CH; t += QPB) {
            const float* p = cb + (size_t)(base + t) * 3;
            sx[t] = negf(p[0]);
            sy[t] = negf(p[1]);
            sz[t] = negf(p[2]);
        }
        __syncthreads();

        const int segbase = base + seg * SEG;

        // Branchless chunk-local tracking for both queries.
        float cbA = INFINITY, cbB = INFINITY;
        int   cgA = 0,        cgB = 0;

        // ---- software pipeline: preload group 0 ----
        ulonglong2 aX0 = sxv[0], aX1 = sxv[1];
        ulonglong2 aY0 = syv[0], aY1 = syv[1];
        ulonglong2 aZ0 = szv[0], aZ1 = szv[1];

        #pragma unroll 4
        for (int g = 0; g < NGRP; ++g) {
            // Prefetch group g+1 while computing g (both queries).
            ulonglong2 nX0, nX1, nY0, nY1, nZ0, nZ1;
            if (g + 1 < NGRP) {
                nX0 = sxv[2 * g + 2]; nX1 = sxv[2 * g + 3];
                nY0 = syv[2 * g + 2]; nY1 = syv[2 * g + 3];
                nZ0 = szv[2 * g + 2]; nZ1 = szv[2 * g + 3];
            }

            // ---- query A ----
            {
                float d0, d1, d2, d3, d4, d5, d6, d7;
                group_dists_v(aX0, aX1, aY0, aY1, aZ0, aZ1,
                              paxx, payy, pazz,
                              d0, d1, d2, d3, d4, d5, d6, d7);
                const float m = fminf(fminf(fminf(d0, d1), fminf(d2, d3)),
                                      fminf(fminf(d4, d5), fminf(d6, d7)));
                const bool imp = m < cbA;
                cbA = imp ? m : cbA;
                cgA = imp ? g : cgA;
            }
            // ---- query B ----
            {
                float d0, d1, d2, d3, d4, d5, d6, d7;
                group_dists_v(aX0, aX1, aY0, aY1, aZ0, aZ1,
                              pbxx, pbyy, pbzz,
                              d0, d1, d2, d3, d4, d5, d6, d7);
                const float m = fminf(fminf(fminf(d0, d1), fminf(d2, d3)),
                                      fminf(fminf(d4, d5), fminf(d6, d7)));
                const bool imp = m < cbB;
                cbB = imp ? m : cbB;
                cgB = imp ? g : cgB;
            }

            aX0 = nX0; aX1 = nX1;
            aY0 = nY0; aY1 = nY1;
            aZ0 = nZ0; aZ1 = nZ1;
        }

        // Rare: recover in-group indices by recomputing the winning group
        // from the SAME smem with the SAME packed ops (bit-exact). Runs
        // before the next chunk's staging sync, so data is still resident.
        if (cbA < bestA) {
            bestA = cbA;
            float d0, d1, d2, d3, d4, d5, d6, d7;
            group_dists_v(sxv[2 * cgA], sxv[2 * cgA + 1],
                          syv[2 * cgA], syv[2 * cgA + 1],
                          szv[2 * cgA], szv[2 * cgA + 1],
                          paxx, payy, pazz,
                          d0, d1, d2, d3, d4, d5, d6, d7);
            biA = group_argmin(cbA, segbase + cgA * 8,
                               d0, d1, d2, d3, d4, d5, d6, d7);
        }
        if (cbB < bestB) {
            bestB = cbB;
            float d0, d1, d2, d3, d4, d5, d6, d7;
            group_dists_v(sxv[2 * cgB], sxv[2 * cgB + 1],
                          syv[2 * cgB], syv[2 * cgB + 1],
                          szv[2 * cgB], szv[2 * cgB + 1],
                          pbxx, pbyy, pbzz,
                          d0, d1, d2, d3, d4, d5, d6, d7);
            biB = group_argmin(cbB, segbase + cgB * 8,
                               d0, d1, d2, d3, d4, d5, d6, d7);
        }
    }

    rbest[seg * NQ_BLK + slot]         = bestA;
    rbi[seg * NQ_BLK + slot]           = biA;
    rbest[seg * NQ_BLK + slot + NSLOT] = bestB;
    rbi[seg * NQ_BLK + slot + NSLOT]   = biB;
    __syncthreads();

    // Combine 8 segments per query: lexicographic (d, idx) min == first occurrence.
    if (tid < NQ_BLK) {
        float bd  = rbest[tid];
        int   bix = rbi[tid];
        #pragma unroll
        for (int s = 1; s < NSEG; ++s) {
            const float od = rbest[s * NQ_BLK + tid];
            const int   oi = rbi[s * NQ_BLK + tid];
            if (od < bd || (od == bd && oi < bix)) { bd = od; bix = oi; }
        }
        const int qo = blockIdx.x * NQ_BLK + tid;
        outd[(size_t)b * Nq + qo] = bd;
        outi[(size_t)b * Nq + qo] = (float)bix;   // <= 8191, exact in fp32
    }
}

extern "C" void kernel_launch(void* const* d_in, const int* in_sizes, int n_in,
                              void* d_out, int out_size)
{
    const float* xyz1 = (const float*)d_in[0];  // [4, 8192, 3]
    const float* xyz2 = (const float*)d_in[1];  // [4, 8192, 3]
    float* out = (float*)d_out;

    const int B = 4;
    const int N = in_sizes[0] / (B * 3);  // 8192
    const int M = in_sizes[1] / (B * 3);  // 8192

    dim3 block(QPB, 1, 1);
    dim3 grid(N / NQ_BLK, B, 2);   // 2048 blocks x 128 threads
    chamfer_kernel<<<grid, block>>>(xyz1, xyz2, out, N, M, B);
}